// round 2
// baseline (speedup 1.0000x reference)
#include <cuda_runtime.h>
#include <cstdint>

// YOLO loss, single fused kernel:
//  - per-block: stage a 128-cell tile of pred+target into padded smem via
//    fully-coalesced float4 loads, compute per-cell loss, block-reduce.
//  - last finishing block reduces all block partials (fixed order -> deterministic)
//    and writes the scalar output. No second launch.
//
// Inputs: d_in[0]=y(pred), d_in[1]=gt(target), each (16384,7,7,30) fp32. Output: 1 fp32.

#define NCELLS   (16384 * 7 * 7)     // 802816
#define TILE     128                 // cells per block
#define NTILES   (NCELLS / TILE)     // 6272 (exact)
#define THREADS  128
#define VEC4S    (TILE * 30 / 4)     // 960 float4 per tensor per tile
#define CPAD     33                  // padded floats per cell in smem (conflict-free)

__device__ float    g_partial[8192];
__device__ unsigned g_count = 0;

__device__ __forceinline__ float iou_f(float x1, float y1, float w1, float h1,
                                       float x2, float y2, float w2, float h2) {
    float xl = fmaxf(x1 - w1 * 0.5f, x2 - w2 * 0.5f);
    float yt = fmaxf(y1 - h1 * 0.5f, y2 - h2 * 0.5f);
    float xr = fminf(x1 + w1 * 0.5f, x2 + w2 * 0.5f);
    float yb = fminf(y1 + h1 * 0.5f, y2 + h2 * 0.5f);
    bool valid = (xr >= xl) && (yb >= yt);
    float inter = (xr - xl) * (yb - yt);
    float uni = w1 * h1 + w2 * h2 - inter;
    float safe = (uni == 0.0f) ? 1.0f : uni;
    return valid ? (inter / safe) : 0.0f;
}

__device__ __forceinline__ void scatter4(float* __restrict__ s, int j, float4 v) {
    // j = float index within tile (cell*30 + c); store into padded layout cell*CPAD + c
    int c0 = j / 30, r0 = j - c0 * 30;
    int j1 = j + 1, c1 = j1 / 30, r1 = j1 - c1 * 30;
    int j2 = j + 2, c2 = j2 / 30, r2 = j2 - c2 * 30;
    int j3 = j + 3, c3 = j3 / 30, r3 = j3 - c3 * 30;
    s[c0 * CPAD + r0] = v.x;
    s[c1 * CPAD + r1] = v.y;
    s[c2 * CPAD + r2] = v.z;
    s[c3 * CPAD + r3] = v.w;
}

__global__ void __launch_bounds__(THREADS)
yolo_fused_kernel(const float* __restrict__ pred,
                  const float* __restrict__ tgt,
                  float* __restrict__ out) {
    __shared__ float sp[TILE * CPAD];   // pred tile, padded
    __shared__ float st[TILE * CPAD];   // target tile, padded
    __shared__ float swarp[THREADS / 32];
    __shared__ int   s_isLast;

    const int tid  = threadIdx.x;
    const int tile = blockIdx.x;

    // ---- stage: fully coalesced float4 loads, scatter to padded smem ----
    const float4* gp = reinterpret_cast<const float4*>(pred) + (size_t)tile * VEC4S;
    const float4* gt = reinterpret_cast<const float4*>(tgt)  + (size_t)tile * VEC4S;
#pragma unroll
    for (int i = tid; i < VEC4S; i += THREADS) {
        float4 vp = gp[i];
        float4 vt = gt[i];
        scatter4(sp, i * 4, vp);
        scatter4(st, i * 4, vt);
    }
    __syncthreads();

    // ---- compute: one cell per thread, conflict-free smem reads ----
    const float* pp = &sp[tid * CPAD];
    const float* tp = &st[tid * CPAD];

    float t0 = tp[0], t1 = tp[1], t2 = tp[2], t3 = tp[3], t4 = tp[4];
    float p0 = pp[0], p1 = pp[1], p2 = pp[2], p3 = pp[3], p4 = pp[4];
    float p5 = pp[5], p6 = pp[6], p7 = pp[7], p8 = pp[8], p9 = pp[9];

    float obj   = (t4 > 0.0f)  ? 1.0f : 0.0f;
    float noobj = (t4 == 0.0f) ? 1.0f : 0.0f;

    float cls = 0.0f;
#pragma unroll
    for (int c = 10; c < 30; c++) {
        float d = tp[c] - pp[c];
        cls += d * d;
    }
    cls *= obj;

    float dno = t4 - p4;
    float conf_noobj = noobj * dno * dno;

    float iou1 = iou_f(t0, t1, t2, t3, p0, p1, p2, p3);
    float iou2 = iou_f(t0, t1, t2, t3, p5, p6, p7, p8);
    float resp1 = (iou1 > iou2) ? 1.0f : 0.0f;
    float m1 = obj * resp1;
    float m2 = obj * (1.0f - resp1);

    float d1 = iou1 - p4;
    float d2 = iou2 - p9;
    float conf_obj = m1 * d1 * d1 + m2 * d2 * d2;

    float dx1 = t0 - p0, dy1 = t1 - p1;
    float dx2 = t0 - p5, dy2 = t1 - p6;
    float xy = m1 * (dx1 * dx1 + dy1 * dy1) + m2 * (dx2 * dx2 + dy2 * dy2);

    float dw1 = t2 - p2, dh1 = t3 - p3;
    float dw2 = t2 - p7, dh2 = t3 - p8;
    float wh = m1 * (dw1 * dw1 + dh1 * dh1) + m2 * (dw2 * dw2 + dh2 * dh2);

    float loss = 5.0f * (xy + wh) + conf_obj + 0.5f * conf_noobj + cls;

    // ---- block reduce ----
#pragma unroll
    for (int off = 16; off > 0; off >>= 1)
        loss += __shfl_down_sync(0xFFFFFFFFu, loss, off);

    int lane = tid & 31, wid = tid >> 5;
    if (lane == 0) swarp[wid] = loss;
    __syncthreads();

    if (tid == 0) {
        float bsum = swarp[0] + swarp[1] + swarp[2] + swarp[3];
        g_partial[tile] = bsum;
        __threadfence();
        unsigned v = atomicAdd(&g_count, 1u);
        s_isLast = (v == (unsigned)(gridDim.x - 1)) ? 1 : 0;
    }
    __syncthreads();

    // ---- last block: deterministic final reduction ----
    if (s_isLast) {
        __shared__ double sd[THREADS];
        double acc = 0.0;
        for (int i = tid; i < NTILES; i += THREADS)
            acc += (double)g_partial[i];
        sd[tid] = acc;
        __syncthreads();
#pragma unroll
        for (int stride = THREADS / 2; stride > 0; stride >>= 1) {
            if (tid < stride) sd[tid] += sd[tid + stride];
            __syncthreads();
        }
        if (tid == 0) {
            out[0] = (float)(sd[0] / 16384.0);
            g_count = 0;   // reset for next graph replay
        }
    }
}

extern "C" void kernel_launch(void* const* d_in, const int* in_sizes, int n_in,
                              void* d_out, int out_size) {
    const float* y  = (const float*)d_in[0];
    const float* gt = (const float*)d_in[1];
    float* out = (float*)d_out;

    yolo_fused_kernel<<<NTILES, THREADS>>>(y, gt, out);
}

// round 3
// speedup vs baseline: 1.0241x; 1.0241x over previous
#include <cuda_runtime.h>
#include <cstdint>

// YOLO loss, single fused kernel, round 3.
// Phase 1: coalesced float4 stream; class channels (10..29, 2/3 of data) are
//          squared-and-differenced in place into per-float4 partial slots
//          (no transpose needed); only pred ch0..9 and tgt ch0..4 staged to smem.
// Phase 2: one cell/thread finishes loss from 15 staged floats + ~5.5 partials.
// Tail:    last finishing block reduces all block partials in fixed order.
// Fully deterministic (no float atomics).

#define NCELLS  (16384 * 7 * 7)      // 802816
#define TILE    512                  // cells per block
#define NTILES  (NCELLS / TILE)      // 1568 (exact)
#define THREADS 256
#define V4      (TILE * 30 / 4)      // 3840 float4 per tensor per tile
#define PER_TH  (V4 / THREADS)       // 15 (exact)

__device__ float    g_partial[4096];
__device__ unsigned g_count = 0;

__device__ __forceinline__ float iou_f(float x1, float y1, float w1, float h1,
                                       float x2, float y2, float w2, float h2) {
    float xl = fmaxf(x1 - w1 * 0.5f, x2 - w2 * 0.5f);
    float yt = fmaxf(y1 - h1 * 0.5f, y2 - h2 * 0.5f);
    float xr = fminf(x1 + w1 * 0.5f, x2 + w2 * 0.5f);
    float yb = fminf(y1 + h1 * 0.5f, y2 + h2 * 0.5f);
    bool valid = (xr >= xl) && (yb >= yt);
    float inter = (xr - xl) * (yb - yt);
    float uni = w1 * h1 + w2 * h2 - inter;
    float safe = (uni == 0.0f) ? 1.0f : uni;
    return valid ? (inter / safe) : 0.0f;
}

__global__ void __launch_bounds__(THREADS, 4)
yolo_fused_kernel(const float* __restrict__ pred,
                  const float* __restrict__ tgt,
                  float* __restrict__ out) {
    __shared__ float sp[TILE * 11];   // pred ch0..9, pad 11 (conflict-free)
    __shared__ float st[TILE * 5];    // tgt  ch0..4, pad 5  (gcd(5,32)=1)
    __shared__ float scls[V4];        // per-float4 class partial sums
    __shared__ float swarp[THREADS / 32];
    __shared__ int   s_isLast;

    const int tid = threadIdx.x;

    // ---- phase 1: coalesced stream + in-flight class reduction ----
    const float4* gp = reinterpret_cast<const float4*>(pred) + (size_t)blockIdx.x * V4;
    const float4* gt = reinterpret_cast<const float4*>(tgt)  + (size_t)blockIdx.x * V4;

    // i = k*256 + tid;  q = i/15 (cell pair), j = i%15. 256 = 17*15 + 1,
    // so per step: q += 17, j += 1 (wrap -> q += 1).
    int q = tid / 15;
    int j = tid - q * 15;

#pragma unroll
    for (int k = 0; k < PER_TH; k++) {
        int i = k * THREADS + tid;
        float4 pv = gp[i];
        float4 tv = gt[i];
        float pe[4] = {pv.x, pv.y, pv.z, pv.w};
        float te[4] = {tv.x, tv.y, tv.z, tv.w};

        int f0 = j * 4;                 // float index within 60-float cell pair
        float cls = 0.0f;
#pragma unroll
        for (int e = 0; e < 4; e++) {
            int f = f0 + e;             // 0..59
            int hi = (f >= 30) ? 1 : 0;
            int cell = 2 * q + hi;      // cell within tile
            int c = f - 30 * hi;        // channel 0..29
            if (c >= 10) {
                float d = te[e] - pe[e];
                cls += d * d;
            } else {
                sp[cell * 11 + c] = pe[e];
                if (c < 5) st[cell * 5 + c] = te[e];
            }
        }
        scls[i] = cls;

        // advance (q, j) for next k
        q += 17; j += 1;
        if (j >= 15) { j -= 15; q += 1; }
    }
    __syncthreads();

    // ---- phase 2: finish loss, 2 cells per thread ----
    float loss = 0.0f;
#pragma unroll
    for (int half = 0; half < 2; half++) {
        int cell = tid + half * THREADS;
        const float* pb = &sp[cell * 11];
        const float* tb = &st[cell * 5];

        float t0 = tb[0], t1 = tb[1], t2 = tb[2], t3 = tb[3], t4 = tb[4];
        float p0 = pb[0], p1 = pb[1], p2 = pb[2], p3 = pb[3], p4 = pb[4];
        float p5 = pb[5], p6 = pb[6], p7 = pb[7], p8 = pb[8], p9 = pb[9];

        // class partial slots:
        //  even cell (pair qq): floats 60qq+10..+29 -> slots 15qq+2 .. 15qq+7  (6)
        //  odd  cell          : floats 60qq+40..+59 -> slots 15qq+10.. 15qq+14 (5)
        int qq = cell >> 1;
        int odd = cell & 1;
        int base = qq * 15 + (odd ? 10 : 2);
        float cls = scls[base] + scls[base + 1] + scls[base + 2]
                  + scls[base + 3] + scls[base + 4];
        if (!odd) cls += scls[base + 5];

        float obj   = (t4 > 0.0f)  ? 1.0f : 0.0f;
        float noobj = (t4 == 0.0f) ? 1.0f : 0.0f;
        cls *= obj;

        float dno = t4 - p4;
        float conf_noobj = noobj * dno * dno;

        float iou1 = iou_f(t0, t1, t2, t3, p0, p1, p2, p3);
        float iou2 = iou_f(t0, t1, t2, t3, p5, p6, p7, p8);
        float resp1 = (iou1 > iou2) ? 1.0f : 0.0f;
        float m1 = obj * resp1;
        float m2 = obj * (1.0f - resp1);

        float d1 = iou1 - p4;
        float d2 = iou2 - p9;
        float conf_obj = m1 * d1 * d1 + m2 * d2 * d2;

        float dx1 = t0 - p0, dy1 = t1 - p1;
        float dx2 = t0 - p5, dy2 = t1 - p6;
        float xy = m1 * (dx1 * dx1 + dy1 * dy1) + m2 * (dx2 * dx2 + dy2 * dy2);

        float dw1 = t2 - p2, dh1 = t3 - p3;
        float dw2 = t2 - p7, dh2 = t3 - p8;
        float wh = m1 * (dw1 * dw1 + dh1 * dh1) + m2 * (dw2 * dw2 + dh2 * dh2);

        loss += 5.0f * (xy + wh) + conf_obj + 0.5f * conf_noobj + cls;
    }

    // ---- block reduce (deterministic) ----
#pragma unroll
    for (int off = 16; off > 0; off >>= 1)
        loss += __shfl_down_sync(0xFFFFFFFFu, loss, off);

    int lane = tid & 31, wid = tid >> 5;
    if (lane == 0) swarp[wid] = loss;
    __syncthreads();

    if (tid == 0) {
        float bsum = 0.0f;
#pragma unroll
        for (int w = 0; w < THREADS / 32; w++) bsum += swarp[w];
        g_partial[blockIdx.x] = bsum;
        __threadfence();
        unsigned v = atomicAdd(&g_count, 1u);
        s_isLast = (v == (unsigned)(gridDim.x - 1)) ? 1 : 0;
    }
    __syncthreads();

    // ---- last block: deterministic final reduction ----
    if (s_isLast) {
        __shared__ double sd[THREADS];
        double acc = 0.0;
        for (int i = tid; i < NTILES; i += THREADS)
            acc += (double)g_partial[i];
        sd[tid] = acc;
        __syncthreads();
#pragma unroll
        for (int stride = THREADS / 2; stride > 0; stride >>= 1) {
            if (tid < stride) sd[tid] += sd[tid + stride];
            __syncthreads();
        }
        if (tid == 0) {
            out[0] = (float)(sd[0] / 16384.0);
            g_count = 0;   // reset for next graph replay
        }
    }
}

extern "C" void kernel_launch(void* const* d_in, const int* in_sizes, int n_in,
                              void* d_out, int out_size) {
    const float* y  = (const float*)d_in[0];
    const float* gt = (const float*)d_in[1];
    float* out = (float*)d_out;

    yolo_fused_kernel<<<NTILES, THREADS>>>(y, gt, out);
}

// round 4
// speedup vs baseline: 1.1921x; 1.1641x over previous
#include <cuda_runtime.h>
#include <cstdint>

// YOLO loss R4: pair-of-cells (60 floats = 15 float4) decomposition.
// Phase 1: branchless coalesced float4 staging (LDG.128 -> STS.128, no decode).
// Phase 2: one thread per cell-pair; static channel mapping per float4 slot;
//          LDS.128 at 60-float lane stride is bank-conflict-free (28 mod 32).
// Tail: last finishing block reduces block partials in fixed order (deterministic).

#define NCELLS  (16384 * 7 * 7)   // 802816
#define TILE    256               // cells per block
#define PAIRS   128               // cell pairs per block
#define THREADS 128
#define V4      (TILE * 30 / 4)   // 1920 float4 per tensor per tile
#define NTILES  (NCELLS / TILE)   // 3136 exact
#define SMEM_BYTES (2 * V4 * 16)  // 61440

__device__ float    g_partial[4096];
__device__ unsigned g_count = 0;

__device__ __forceinline__ float iou_f(float x1, float y1, float w1, float h1,
                                       float x2, float y2, float w2, float h2) {
    float xl = fmaxf(x1 - w1 * 0.5f, x2 - w2 * 0.5f);
    float yt = fmaxf(y1 - h1 * 0.5f, y2 - h2 * 0.5f);
    float xr = fminf(x1 + w1 * 0.5f, x2 + w2 * 0.5f);
    float yb = fminf(y1 + h1 * 0.5f, y2 + h2 * 0.5f);
    bool valid = (xr >= xl) && (yb >= yt);
    float inter = (xr - xl) * (yb - yt);
    float uni = w1 * h1 + w2 * h2 - inter;
    float safe = (uni == 0.0f) ? 1.0f : uni;
    return valid ? (inter / safe) : 0.0f;
}

// One cell's non-class loss given its 15 box/conf floats + its class sum.
__device__ __forceinline__ float cell_loss(float t0, float t1, float t2, float t3, float t4,
                                           float p0, float p1, float p2, float p3, float p4,
                                           float p5, float p6, float p7, float p8, float p9,
                                           float cls) {
    float obj   = (t4 > 0.0f)  ? 1.0f : 0.0f;
    float noobj = (t4 == 0.0f) ? 1.0f : 0.0f;

    float dno = t4 - p4;
    float conf_noobj = noobj * dno * dno;

    float iou1 = iou_f(t0, t1, t2, t3, p0, p1, p2, p3);
    float iou2 = iou_f(t0, t1, t2, t3, p5, p6, p7, p8);
    float resp1 = (iou1 > iou2) ? 1.0f : 0.0f;
    float m1 = obj * resp1;
    float m2 = obj * (1.0f - resp1);

    float d1 = iou1 - p4;
    float d2 = iou2 - p9;
    float conf_obj = m1 * d1 * d1 + m2 * d2 * d2;

    float dx1 = t0 - p0, dy1 = t1 - p1;
    float dx2 = t0 - p5, dy2 = t1 - p6;
    float xy = m1 * (dx1 * dx1 + dy1 * dy1) + m2 * (dx2 * dx2 + dy2 * dy2);

    float dw1 = t2 - p2, dh1 = t3 - p3;
    float dw2 = t2 - p7, dh2 = t3 - p8;
    float wh = m1 * (dw1 * dw1 + dh1 * dh1) + m2 * (dw2 * dw2 + dh2 * dh2);

    return 5.0f * (xy + wh) + conf_obj + 0.5f * conf_noobj + obj * cls;
}

__global__ void __launch_bounds__(THREADS)
yolo_fused_kernel(const float* __restrict__ pred,
                  const float* __restrict__ tgt,
                  float* __restrict__ out) {
    extern __shared__ float4 sm[];
    float4* sp4 = sm;        // pred tile, raw float4
    float4* st4 = sm + V4;   // tgt tile, raw float4
    __shared__ float swarp[THREADS / 32];
    __shared__ int   s_isLast;

    const int tid = threadIdx.x;
    const float4* gp = reinterpret_cast<const float4*>(pred) + (size_t)blockIdx.x * V4;
    const float4* gt = reinterpret_cast<const float4*>(tgt)  + (size_t)blockIdx.x * V4;

    // ---- phase 1: branchless staging, loads batched for MLP ----
    {
        float4 rp[8], rt[8];
#pragma unroll
        for (int k = 0; k < 8; k++) { rp[k] = gp[k * THREADS + tid]; rt[k] = gt[k * THREADS + tid]; }
#pragma unroll
        for (int k = 0; k < 8; k++) { sp4[k * THREADS + tid] = rp[k]; st4[k * THREADS + tid] = rt[k]; }
#pragma unroll
        for (int k = 8; k < 15; k++) { rp[k - 8] = gp[k * THREADS + tid]; rt[k - 8] = gt[k * THREADS + tid]; }
#pragma unroll
        for (int k = 8; k < 15; k++) { sp4[k * THREADS + tid] = rp[k - 8]; st4[k * THREADS + tid] = rt[k - 8]; }
    }
    __syncthreads();

    // ---- phase 2: one pair per thread, static slot->channel mapping ----
    // Pair floats 0..59: even cell = 0..29, odd cell = 30..59.
    const float4* SP = sp4 + tid * 15;
    const float4* ST = st4 + tid * 15;

    // even-cell class (e12..e27 in j3..j6; e10,e11 in j2.zw; e28,e29 in j7.xy)
    float cls_e = 0.0f;
#pragma unroll
    for (int j = 3; j <= 6; j++) {
        float4 a = ST[j], b = SP[j];
        float d0 = a.x - b.x, d1 = a.y - b.y, d2 = a.z - b.z, d3 = a.w - b.w;
        cls_e += d0 * d0 + d1 * d1 + d2 * d2 + d3 * d3;
    }
    float4 P2 = SP[2], T2 = ST[2];
    { float d0 = T2.z - P2.z, d1 = T2.w - P2.w; cls_e += d0 * d0 + d1 * d1; }
    float4 P7 = SP[7], T7 = ST[7];
    { float d0 = T7.x - P7.x, d1 = T7.y - P7.y; cls_e += d0 * d0 + d1 * d1; }

    // odd-cell class (o10..o29 = j10..j14, full vectors)
    float cls_o = 0.0f;
#pragma unroll
    for (int j = 10; j <= 14; j++) {
        float4 a = ST[j], b = SP[j];
        float d0 = a.x - b.x, d1 = a.y - b.y, d2 = a.z - b.z, d3 = a.w - b.w;
        cls_o += d0 * d0 + d1 * d1 + d2 * d2 + d3 * d3;
    }

    float4 P0 = SP[0], P1 = SP[1], T0 = ST[0], T1 = ST[1];
    float4 P8 = SP[8], P9 = SP[9], T8 = ST[8];

    // even cell: t0..t4 = T0.xyzw,T1.x ; p0..p9 = P0.xyzw,P1.xyzw,P2.xy
    float loss = cell_loss(T0.x, T0.y, T0.z, T0.w, T1.x,
                           P0.x, P0.y, P0.z, P0.w, P1.x,
                           P1.y, P1.z, P1.w, P2.x, P2.y, cls_e);
    // odd cell: t0..t4 = T7.zw,T8.xyz ; p0..p9 = P7.zw,P8.xyzw,P9.xyzw
    loss      += cell_loss(T7.z, T7.w, T8.x, T8.y, T8.z,
                           P7.z, P7.w, P8.x, P8.y, P8.z,
                           P8.w, P9.x, P9.y, P9.z, P9.w, cls_o);

    // ---- block reduce (deterministic) ----
#pragma unroll
    for (int off = 16; off > 0; off >>= 1)
        loss += __shfl_down_sync(0xFFFFFFFFu, loss, off);

    int lane = tid & 31, wid = tid >> 5;
    if (lane == 0) swarp[wid] = loss;
    __syncthreads();

    if (tid == 0) {
        float bsum = swarp[0] + swarp[1] + swarp[2] + swarp[3];
        g_partial[blockIdx.x] = bsum;
        __threadfence();
        unsigned v = atomicAdd(&g_count, 1u);
        s_isLast = (v == (unsigned)(gridDim.x - 1)) ? 1 : 0;
    }
    __syncthreads();

    // ---- last block: deterministic final reduction ----
    if (s_isLast) {
        __shared__ double sd[THREADS];
        double acc = 0.0;
        for (int i = tid; i < NTILES; i += THREADS)
            acc += (double)g_partial[i];
        sd[tid] = acc;
        __syncthreads();
#pragma unroll
        for (int stride = THREADS / 2; stride > 0; stride >>= 1) {
            if (tid < stride) sd[tid] += sd[tid + stride];
            __syncthreads();
        }
        if (tid == 0) {
            out[0] = (float)(sd[0] / 16384.0);
            g_count = 0;   // reset for next graph replay
        }
    }
}

extern "C" void kernel_launch(void* const* d_in, const int* in_sizes, int n_in,
                              void* d_out, int out_size) {
    const float* y  = (const float*)d_in[0];
    const float* gt = (const float*)d_in[1];
    float* out = (float*)d_out;

    static int attr_done = 0;
    if (!attr_done) {
        cudaFuncSetAttribute(yolo_fused_kernel,
                             cudaFuncAttributeMaxDynamicSharedMemorySize, SMEM_BYTES);
        attr_done = 1;
    }

    yolo_fused_kernel<<<NTILES, THREADS, SMEM_BYTES>>>(y, gt, out);
}

// round 5
// speedup vs baseline: 1.5313x; 1.2845x over previous
#include <cuda_runtime.h>
#include <cstdint>

// YOLO loss R5: persistent blocks + cp.async double-buffered tile pipeline.
// Prefetch tile k+1 (GMEM->SMEM via LDGSTS, L1-bypass) while computing tile k.
// Compute keeps R4's static pair-of-cells mapping (60 floats = 15 float4).
// Deterministic: fixed tile->block map, fixed-order final reduction.

#define NCELLS  (16384 * 7 * 7)    // 802816
#define TILE_C  128                // cells per tile
#define PAIRS   64                 // cell pairs per tile
#define THREADS 128
#define TV4     (TILE_C * 30 / 4)  // 960 float4 per tensor per tile
#define STAGE_V4 (2 * TV4)         // 1920 float4 per stage (pred + tgt)
#define NTILES  (NCELLS / TILE_C)  // 6272 exact
#define GRID    456                // persistent blocks (~3/SM)
#define SMEM_BYTES (2 * STAGE_V4 * 16)  // 61440

__device__ float    g_partial[4096];
__device__ unsigned g_count = 0;

__device__ __forceinline__ void cp_async16(void* smem_dst, const void* gmem_src) {
    unsigned saddr = (unsigned)__cvta_generic_to_shared(smem_dst);
    asm volatile("cp.async.cg.shared.global [%0], [%1], 16;\n"
                 :: "r"(saddr), "l"(gmem_src) : "memory");
}
__device__ __forceinline__ void cp_commit() {
    asm volatile("cp.async.commit_group;\n" ::: "memory");
}
template <int N>
__device__ __forceinline__ void cp_wait() {
    asm volatile("cp.async.wait_group %0;\n" :: "n"(N) : "memory");
}

__device__ __forceinline__ float iou_f(float x1, float y1, float w1, float h1,
                                       float x2, float y2, float w2, float h2) {
    float xl = fmaxf(x1 - w1 * 0.5f, x2 - w2 * 0.5f);
    float yt = fmaxf(y1 - h1 * 0.5f, y2 - h2 * 0.5f);
    float xr = fminf(x1 + w1 * 0.5f, x2 + w2 * 0.5f);
    float yb = fminf(y1 + h1 * 0.5f, y2 + h2 * 0.5f);
    bool valid = (xr >= xl) && (yb >= yt);
    float inter = (xr - xl) * (yb - yt);
    float uni = w1 * h1 + w2 * h2 - inter;
    float safe = (uni == 0.0f) ? 1.0f : uni;
    return valid ? (inter / safe) : 0.0f;
}

__device__ __forceinline__ float cell_loss(float t0, float t1, float t2, float t3, float t4,
                                           float p0, float p1, float p2, float p3, float p4,
                                           float p5, float p6, float p7, float p8, float p9,
                                           float cls) {
    float obj   = (t4 > 0.0f)  ? 1.0f : 0.0f;
    float noobj = (t4 == 0.0f) ? 1.0f : 0.0f;

    float dno = t4 - p4;
    float conf_noobj = noobj * dno * dno;

    float iou1 = iou_f(t0, t1, t2, t3, p0, p1, p2, p3);
    float iou2 = iou_f(t0, t1, t2, t3, p5, p6, p7, p8);
    float resp1 = (iou1 > iou2) ? 1.0f : 0.0f;
    float m1 = obj * resp1;
    float m2 = obj * (1.0f - resp1);

    float d1 = iou1 - p4;
    float d2 = iou2 - p9;
    float conf_obj = m1 * d1 * d1 + m2 * d2 * d2;

    float dx1 = t0 - p0, dy1 = t1 - p1;
    float dx2 = t0 - p5, dy2 = t1 - p6;
    float xy = m1 * (dx1 * dx1 + dy1 * dy1) + m2 * (dx2 * dx2 + dy2 * dy2);

    float dw1 = t2 - p2, dh1 = t3 - p3;
    float dw2 = t2 - p7, dh2 = t3 - p8;
    float wh = m1 * (dw1 * dw1 + dh1 * dh1) + m2 * (dw2 * dw2 + dh2 * dh2);

    return 5.0f * (xy + wh) + conf_obj + 0.5f * conf_noobj + obj * cls;
}

// Prefetch one tile into stage s: 1920 float4 (pred then tgt), 15 per thread.
__device__ __forceinline__ void prefetch_tile(float4* sbuf, int s,
                                              const float4* __restrict__ gp,
                                              const float4* __restrict__ gt,
                                              int tile, int tid) {
    float4* dst = sbuf + s * STAGE_V4;
    const float4* srcp = gp + (size_t)tile * TV4;
    const float4* srct = gt + (size_t)tile * TV4;
#pragma unroll
    for (int k = 0; k < 15; k++) {
        int i = k * THREADS + tid;               // 0..1919
        const float4* src = (i < TV4) ? (srcp + i) : (srct + (i - TV4));
        cp_async16(dst + i, src);
    }
}

// Compute one pair (static slot->channel mapping) from staged tile.
__device__ __forceinline__ float pair_loss(const float4* __restrict__ SP,
                                           const float4* __restrict__ ST) {
    float cls_e = 0.0f;
#pragma unroll
    for (int j = 3; j <= 6; j++) {
        float4 a = ST[j], b = SP[j];
        float d0 = a.x - b.x, d1 = a.y - b.y, d2 = a.z - b.z, d3 = a.w - b.w;
        cls_e += d0 * d0 + d1 * d1 + d2 * d2 + d3 * d3;
    }
    float4 P2 = SP[2], T2 = ST[2];
    { float d0 = T2.z - P2.z, d1 = T2.w - P2.w; cls_e += d0 * d0 + d1 * d1; }
    float4 P7 = SP[7], T7 = ST[7];
    { float d0 = T7.x - P7.x, d1 = T7.y - P7.y; cls_e += d0 * d0 + d1 * d1; }

    float cls_o = 0.0f;
#pragma unroll
    for (int j = 10; j <= 14; j++) {
        float4 a = ST[j], b = SP[j];
        float d0 = a.x - b.x, d1 = a.y - b.y, d2 = a.z - b.z, d3 = a.w - b.w;
        cls_o += d0 * d0 + d1 * d1 + d2 * d2 + d3 * d3;
    }

    float4 P0 = SP[0], P1 = SP[1], T0 = ST[0], T1 = ST[1];
    float4 P8 = SP[8], P9 = SP[9], T8 = ST[8];

    float l = cell_loss(T0.x, T0.y, T0.z, T0.w, T1.x,
                        P0.x, P0.y, P0.z, P0.w, P1.x,
                        P1.y, P1.z, P1.w, P2.x, P2.y, cls_e);
    l      += cell_loss(T7.z, T7.w, T8.x, T8.y, T8.z,
                        P7.z, P7.w, P8.x, P8.y, P8.z,
                        P8.w, P9.x, P9.y, P9.z, P9.w, cls_o);
    return l;
}

__global__ void __launch_bounds__(THREADS)
yolo_fused_kernel(const float* __restrict__ pred,
                  const float* __restrict__ tgt,
                  float* __restrict__ out) {
    extern __shared__ float4 sbuf[];       // 2 stages x (960 pred + 960 tgt)
    __shared__ float swarp[THREADS / 32];
    __shared__ int   s_isLast;

    const int tid = threadIdx.x;
    const float4* gp = reinterpret_cast<const float4*>(pred);
    const float4* gt = reinterpret_cast<const float4*>(tgt);

    float loss = 0.0f;

    int t = blockIdx.x;
    int stage = 0;
    if (t < NTILES) prefetch_tile(sbuf, 0, gp, gt, t, tid);
    cp_commit();

    while (t < NTILES) {
        int tn = t + GRID;
        if (tn < NTILES) {
            prefetch_tile(sbuf, stage ^ 1, gp, gt, tn, tid);
            cp_commit();
            cp_wait<1>();           // current tile's group has landed
        } else {
            cp_wait<0>();
        }
        __syncthreads();

        if (tid < PAIRS) {
            const float4* SP = sbuf + stage * STAGE_V4 + tid * 15;
            const float4* ST = SP + TV4;
            loss += pair_loss(SP, ST);
        }
        __syncthreads();            // done reading before this buffer is re-filled
        stage ^= 1;
        t = tn;
    }

    // ---- block reduce (deterministic) ----
#pragma unroll
    for (int off = 16; off > 0; off >>= 1)
        loss += __shfl_down_sync(0xFFFFFFFFu, loss, off);

    int lane = tid & 31, wid = tid >> 5;
    if (lane == 0) swarp[wid] = loss;
    __syncthreads();

    if (tid == 0) {
        float bsum = swarp[0] + swarp[1] + swarp[2] + swarp[3];
        g_partial[blockIdx.x] = bsum;
        __threadfence();
        unsigned v = atomicAdd(&g_count, 1u);
        s_isLast = (v == (unsigned)(gridDim.x - 1)) ? 1 : 0;
    }
    __syncthreads();

    // ---- last block: deterministic final reduction ----
    if (s_isLast) {
        __shared__ double sd[THREADS];
        double acc = 0.0;
        for (int i = tid; i < GRID; i += THREADS)
            acc += (double)g_partial[i];
        sd[tid] = acc;
        __syncthreads();
#pragma unroll
        for (int stride = THREADS / 2; stride > 0; stride >>= 1) {
            if (tid < stride) sd[tid] += sd[tid + stride];
            __syncthreads();
        }
        if (tid == 0) {
            out[0] = (float)(sd[0] / 16384.0);
            g_count = 0;   // reset for next graph replay
        }
    }
}

extern "C" void kernel_launch(void* const* d_in, const int* in_sizes, int n_in,
                              void* d_out, int out_size) {
    const float* y  = (const float*)d_in[0];
    const float* gt = (const float*)d_in[1];
    float* out = (float*)d_out;

    static int attr_done = 0;
    if (!attr_done) {
        cudaFuncSetAttribute(yolo_fused_kernel,
                             cudaFuncAttributeMaxDynamicSharedMemorySize, SMEM_BYTES);
        attr_done = 1;
    }

    yolo_fused_kernel<<<GRID, THREADS, SMEM_BYTES>>>(y, gt, out);
}